// round 17
// baseline (speedup 1.0000x reference)
#include <cuda_runtime.h>
#include <stdint.h>

// Problem shape (fixed per reference setup_inputs):
//   input [B=32, T=1024, H=32, W=32] spike ids in [0, 32)
//   out   [B, 32, H, W] float32 counts over T  (harness output dtype = f32)
static constexpr int B_      = 32;
static constexpr int T_      = 1024;
static constexpr int HW_     = 1024;            // H*W
static constexpr int S_      = 32;              // dim_s
static constexpr int THREADS = 256;             // 8 warps
static constexpr int TSPLIT  = 8;               // warps per block = t-chunks
static constexpr int TCHUNK  = T_ / TSPLIT;     // 128 -> u8 counts safe
static constexpr int PIXBLK  = 128;             // pixels per block
static constexpr int GX      = HW_ / PIXBLK;    // 8
static constexpr int UNROLL  = 8;               // int4 loads deep (32 values)
static constexpr int NBATCH  = TCHUNK / UNROLL; // 16

// Bin s of pixel-slot k (0..3) -> private byte address. Disjoint bits:
//   s&3 -> bits 0..1, col=tid*4 -> bits 2..9, (s&28)<<8 -> bits 10..12,
//   k   -> bits 13..14.   s*257 = (s<<8)|s, no carry for s<32.
// Mask 0x1C03 hard-bounds the smem index for ANY input content.
__device__ __forceinline__ unsigned bin_addr(unsigned colk, unsigned s) {
    return ((s * 257u) & 0x1C03u) | colk;
}

// Block (gg, b) exclusively owns pixels [gg*128, gg*128+128) of batch b for
// ALL T -> plain exactly-once stores, no atomics, no zero-fill, one launch.
//
// warp = t-chunk of 128; lane reads int4 (4 consecutive pixels): per t a warp
// reads 512B CONTIGUOUS, and successive t's are adjacent 4KB rows -> each
// warp streams a contiguous region with LDG.128 (4 lines per LSU queue entry).
//
// Private histogram per thread: 4 pixels x 32 bins u8 -> 32 words, layout
// word (k*8 + (s>>2))*256 + tid: bank = tid%32, conflict-free, thread-private.
__global__ __launch_bounds__(THREADS)
void spike_hist_vec_kernel(const int* __restrict__ in, float* __restrict__ out) {
    __shared__ uint32_t sh[32 * THREADS];   // 32 KB
    unsigned char* __restrict__ shb = reinterpret_cast<unsigned char*>(sh);

    const int tid  = threadIdx.x;
    const int warp = tid >> 5;              // t-chunk 0..7
    const int lane = tid & 31;
    const int gg   = blockIdx.x;            // pixel group 0..7
    const int b    = blockIdx.y;            // batch 0..31

    #pragma unroll
    for (int i = 0; i < 32; i++) sh[i * THREADS + tid] = 0u;

    const int4* p = reinterpret_cast<const int4*>(
        in + (size_t)b * (size_t)(T_ * HW_)
           + (size_t)(warp * TCHUNK) * HW_
           + gg * PIXBLK) + lane;            // int4 stride along t = HW_/4

    const unsigned col = (unsigned)tid * 4u;

    // Batch 0: load UNROLL int4 (32 values), sniff encoding from raw OR.
    int4 v[UNROLL];
    #pragma unroll
    for (int u = 0; u < UNROLL; u++) v[u] = __ldcg(&p[u * (HW_ / 4)]);

    unsigned m = 0;
    #pragma unroll
    for (int u = 0; u < UNROLL; u++)
        m |= (unsigned)(v[u].x | v[u].y | v[u].z | v[u].w);

    if (m < 32u) {
        // ---- int32 ids (expected): zero decode instructions ----
        #pragma unroll
        for (int u = 0; u < UNROLL; u++) {
            shb[bin_addr(col,               (unsigned)v[u].x)]++;
            shb[bin_addr(col + (1u << 13),  (unsigned)v[u].y)]++;
            shb[bin_addr(col + (2u << 13),  (unsigned)v[u].z)]++;
            shb[bin_addr(col + (3u << 13),  (unsigned)v[u].w)]++;
        }
        #pragma unroll 1
        for (int bt = 1; bt < NBATCH; bt++) {
            const int4* q = p + bt * UNROLL * (HW_ / 4);
            #pragma unroll
            for (int u = 0; u < UNROLL; u++) v[u] = __ldcg(&q[u * (HW_ / 4)]);
            #pragma unroll
            for (int u = 0; u < UNROLL; u++) {
                shb[bin_addr(col,               (unsigned)v[u].x)]++;
                shb[bin_addr(col + (1u << 13),  (unsigned)v[u].y)]++;
                shb[bin_addr(col + (2u << 13),  (unsigned)v[u].z)]++;
                shb[bin_addr(col + (3u << 13),  (unsigned)v[u].w)]++;
            }
        }
    } else {
        // ---- float32-encoded ids: per-element convert (mask keeps smem safe) ----
        #pragma unroll 1
        for (int bt = 0; bt < NBATCH; bt++) {
            if (bt > 0) {
                const int4* q = p + bt * UNROLL * (HW_ / 4);
                #pragma unroll
                for (int u = 0; u < UNROLL; u++) v[u] = __ldcg(&q[u * (HW_ / 4)]);
            }
            #pragma unroll
            for (int u = 0; u < UNROLL; u++) {
                int raw[4] = { v[u].x, v[u].y, v[u].z, v[u].w };
                #pragma unroll
                for (int k = 0; k < 4; k++) {
                    const unsigned s = ((unsigned)raw[k] < 32u)
                        ? (unsigned)raw[k]
                        : (unsigned)(int)__int_as_float(raw[k]);
                    shb[bin_addr(col + ((unsigned)k << 13), s)]++;
                }
            }
        }
    }

    __syncthreads();

    // Epilogue: 4096 outputs (128 pixels x 32 bins), 16 per thread.
    // Thread e: pixel pe = e&127, bin-quads q = (e>>7)*4 + j (j=0..3).
    // Sum the 8 t-chunk sub-histograms; stores coalesced (lanes = consecutive
    // pixels), exactly once.
    const int pe = tid & 127;                 // pixel within block
    const int qh = (tid >> 7) * 4;            // first bin-quad (0 or 4)
    const int wbase = (pe & 3) * 8;           // k*8 word offset
    const int owner0 = pe >> 2;               // owner tid = c*32 + (pe>>2)

    float* __restrict__ o =
        out + (size_t)b * (size_t)(S_ * HW_) + gg * PIXBLK + pe;

    #pragma unroll
    for (int j = 0; j < 4; j++) {
        const int q = qh + j;                  // bin-quad: bins 4q..4q+3
        unsigned c0 = 0, c1 = 0, c2 = 0, c3 = 0;
        #pragma unroll
        for (int c = 0; c < TSPLIT; c++) {
            const uint32_t word = sh[(wbase + q) * THREADS + c * 32 + owner0];
            c0 += (word      ) & 0xFFu;
            c1 += (word >>  8) & 0xFFu;
            c2 += (word >> 16) & 0xFFu;
            c3 += (word >> 24);
        }
        o[(size_t)(4 * q + 0) * HW_] = (float)c0;
        o[(size_t)(4 * q + 1) * HW_] = (float)c1;
        o[(size_t)(4 * q + 2) * HW_] = (float)c2;
        o[(size_t)(4 * q + 3) * HW_] = (float)c3;
    }
}

extern "C" void kernel_launch(void* const* d_in, const int* in_sizes, int n_in,
                              void* d_out, int out_size) {
    // Input selection: largest buffer = spike array (never the dim_s scalar).
    int best = 0;
    for (int i = 1; i < n_in; i++) {
        if (in_sizes[i] > in_sizes[best]) best = i;
    }
    const int* in  = (const int*)d_in[best];
    float*     out = (float*)d_out;

    dim3 grid(GX, B_);   // (8, 32) = 256 blocks, 32KB smem each
    spike_hist_vec_kernel<<<grid, THREADS>>>(in, out);
}